// round 5
// baseline (speedup 1.0000x reference)
#include <cuda_runtime.h>
#include <cuda_fp16.h>
#include <math.h>

#define NN 50000
#define NE 800000
#define F  128
#define RPB 64            // rows per block in GEMM
#define HT_STRIDE 68      // transposed h tile stride (mult of 4 -> 16B-aligned pairs)

// ---------------- scratch (device globals; no allocation allowed) ----------
__device__ __align__(16) __half g_feath[NN * F];   // fp16 feat for the gather
__device__ __align__(16) float g_h1[NN * F];
__device__ __align__(16) float g_h2[NN * F];
__device__ __align__(16) float g_el[NN * 4];
__device__ __align__(16) float g_er[NN * 4];
__device__ int g_rowptr[NN + 1];

// ---------------- f32x2 packed-math helpers (sm_10x dual fp32 pipe) --------
__device__ __forceinline__ unsigned long long pack2(float lo, float hi) {
    unsigned long long r;
    asm("mov.b64 %0, {%1, %2};" : "=l"(r) : "f"(lo), "f"(hi));
    return r;
}
__device__ __forceinline__ void unpack2(unsigned long long v, float& lo, float& hi) {
    asm("mov.b64 {%0, %1}, %2;" : "=f"(lo), "=f"(hi) : "l"(v));
}
__device__ __forceinline__ unsigned long long fma2(
    unsigned long long a, unsigned long long b, unsigned long long c) {
    unsigned long long d;
    asm("fma.rn.f32x2 %0, %1, %2, %3;" : "=l"(d) : "l"(a), "l"(b), "l"(c));
    return d;
}

// ---------------- row_ptr from sorted dst via lower_bound ------------------
__global__ void rowptr_kernel(const int* __restrict__ dst) {
    int n = blockIdx.x * blockDim.x + threadIdx.x;
    if (n > NN) return;
    int lo = 0, hi = NE;
    while (lo < hi) {
        int mid = (lo + hi) >> 1;
        if (dst[mid] < n) lo = mid + 1; else hi = mid;
    }
    g_rowptr[n] = lo;
}

// ---------------- register-tiled GEMM (feat = h @ W) + el/er projections ---
// 64 rows x 128 cols per block, 256 threads, 3 blocks/SM. W streamed via LDG
// (L1-resident, 64KB). h tile transposed in shared; row-pairs are f32x2
// accumulator halves loaded as LDS.128 (ulonglong2). Epilogue emits fp16 feat.
__global__ __launch_bounds__(256, 3) void gemm_attn_kernel(
    const float* __restrict__ hin, const float* __restrict__ W,
    const float* __restrict__ al, const float* __restrict__ ar)
{
    __shared__ float hsT[F * HT_STRIDE];       // 34.8 KB
    const int tid  = threadIdx.x;
    const int base = blockIdx.x * RPB;

    // ---- load h tile, store transposed ----
    {
        const int k4 = tid & 31, r0 = tid >> 5;
        #pragma unroll
        for (int j = 0; j < 8; j++) {
            int r = r0 + 8 * j;
            int n = base + r;
            float4 v = (n < NN)
                ? *reinterpret_cast<const float4*>(&hin[n * F + 4 * k4])
                : make_float4(0.f, 0.f, 0.f, 0.f);
            hsT[(4 * k4 + 0) * HT_STRIDE + r] = v.x;
            hsT[(4 * k4 + 1) * HT_STRIDE + r] = v.y;
            hsT[(4 * k4 + 2) * HT_STRIDE + r] = v.z;
            hsT[(4 * k4 + 3) * HT_STRIDE + r] = v.w;
        }
    }
    __syncthreads();

    const int cg = tid & 31;        // column group: cols 4cg..4cg+3
    const int w  = tid >> 5;        // warp: local rows 8w..8w+7
    const int hb = 8 * w;

    unsigned long long acc[4][4];   // [row-pair][col]
    #pragma unroll
    for (int rp = 0; rp < 4; rp++)
        #pragma unroll
        for (int c = 0; c < 4; c++) acc[rp][c] = 0ull;

    const float4* Wg = reinterpret_cast<const float4*>(W);   // Wg[k*32 + cg]

    #pragma unroll 4
    for (int k = 0; k < F; k++) {
        float4 wv = __ldg(&Wg[k * 32 + cg]);
        unsigned long long wp0 = pack2(wv.x, wv.x);
        unsigned long long wp1 = pack2(wv.y, wv.y);
        unsigned long long wp2 = pack2(wv.z, wv.z);
        unsigned long long wp3 = pack2(wv.w, wv.w);
        const ulonglong2* hp =
            reinterpret_cast<const ulonglong2*>(&hsT[k * HT_STRIDE + hb]);
        ulonglong2 hA = hp[0];     // rows (hb, hb+1), (hb+2, hb+3)
        ulonglong2 hB = hp[1];     // rows (hb+4, hb+5), (hb+6, hb+7)
        acc[0][0] = fma2(hA.x, wp0, acc[0][0]);
        acc[0][1] = fma2(hA.x, wp1, acc[0][1]);
        acc[0][2] = fma2(hA.x, wp2, acc[0][2]);
        acc[0][3] = fma2(hA.x, wp3, acc[0][3]);
        acc[1][0] = fma2(hA.y, wp0, acc[1][0]);
        acc[1][1] = fma2(hA.y, wp1, acc[1][1]);
        acc[1][2] = fma2(hA.y, wp2, acc[1][2]);
        acc[1][3] = fma2(hA.y, wp3, acc[1][3]);
        acc[2][0] = fma2(hB.x, wp0, acc[2][0]);
        acc[2][1] = fma2(hB.x, wp1, acc[2][1]);
        acc[2][2] = fma2(hB.x, wp2, acc[2][2]);
        acc[2][3] = fma2(hB.x, wp3, acc[2][3]);
        acc[3][0] = fma2(hB.y, wp0, acc[3][0]);
        acc[3][1] = fma2(hB.y, wp1, acc[3][1]);
        acc[3][2] = fma2(hB.y, wp2, acc[3][2]);
        acc[3][3] = fma2(hB.y, wp3, acc[3][3]);
    }

    // ---- epilogue: store fp16 feat, compute per-head el/er (fp32 exact) ---
    const float4 alv = *reinterpret_cast<const float4*>(&al[4 * cg]);
    const float4 arv = *reinterpret_cast<const float4*>(&ar[4 * cg]);
    const int head = cg >> 3;
    uint2* feath8 = reinterpret_cast<uint2*>(g_feath);   // 4 halfs per lane slot

    #pragma unroll
    for (int rp = 0; rp < 4; rp++) {
        float a0[2], a1[2], a2[2], a3[2];
        unpack2(acc[rp][0], a0[0], a0[1]);
        unpack2(acc[rp][1], a1[0], a1[1]);
        unpack2(acc[rp][2], a2[0], a2[1]);
        unpack2(acc[rp][3], a3[0], a3[1]);
        #pragma unroll
        for (int rr = 0; rr < 2; rr++) {
            float sl = fmaf(a0[rr], alv.x, fmaf(a1[rr], alv.y,
                       fmaf(a2[rr], alv.z, a3[rr] * alv.w)));
            float sr = fmaf(a0[rr], arv.x, fmaf(a1[rr], arv.y,
                       fmaf(a2[rr], arv.z, a3[rr] * arv.w)));
            #pragma unroll
            for (int off = 1; off < 8; off <<= 1) {
                sl += __shfl_xor_sync(0xffffffffu, sl, off);
                sr += __shfl_xor_sync(0xffffffffu, sr, off);
            }
            int n = base + hb + 2 * rp + rr;
            if (n < NN) {
                __half2 p01 = __floats2half2_rn(a0[rr], a1[rr]);
                __half2 p23 = __floats2half2_rn(a2[rr], a3[rr]);
                uint2 pk;
                pk.x = *reinterpret_cast<unsigned*>(&p01);
                pk.y = *reinterpret_cast<unsigned*>(&p23);
                feath8[n * 32 + cg] = pk;
                if ((cg & 7) == 0) {
                    g_el[n * 4 + head] = sl;
                    g_er[n * 4 + head] = sr;
                }
            }
        }
    }
}

// ---------------- per-dst-node edge softmax + weighted aggregation ---------
// One warp per dst node; lane owns 4 features (fp16 gather, fp32 math).
__global__ __launch_bounds__(256) void gat_agg_kernel(
    const int* __restrict__ src,
    const float* __restrict__ hres,   // residual input (may be null)
    float* __restrict__ out,
    int do_act, int do_mean)
{
    const int gw = (blockIdx.x * blockDim.x + threadIdx.x) >> 5;
    if (gw >= NN) return;
    const int lane = threadIdx.x & 31;
    const int n = gw;
    const int e0 = g_rowptr[n];
    const int e1 = g_rowptr[n + 1];
    const int head = lane >> 3;
    const float ern = g_er[n * 4 + head];

    // pass 1: per-head max (redundant per 8-lane group; no reduce needed)
    float m = -1e30f;
    #pragma unroll 4
    for (int i = e0; i < e1; i++) {
        int s = __ldg(&src[i]);
        float e = __ldg(&g_el[s * 4 + head]) + ern;
        e = (e > 0.f) ? e : 0.2f * e;          // leaky_relu(0.2)
        m = fmaxf(m, e);
    }

    // pass 2: exp / sum / weighted fp16 gather-accumulate (fp32 acc)
    float ssum = 0.f;
    float4 acc = make_float4(0.f, 0.f, 0.f, 0.f);
    const uint2* feat8 = reinterpret_cast<const uint2*>(g_feath);
    #pragma unroll 4
    for (int i = e0; i < e1; i++) {
        int s = __ldg(&src[i]);
        float e = __ldg(&g_el[s * 4 + head]) + ern;
        e = (e > 0.f) ? e : 0.2f * e;
        float wgt = __expf(e - m);
        ssum += wgt;
        uint2 pk = __ldg(&feat8[s * 32 + lane]);
        float2 f01 = __half22float2(*reinterpret_cast<__half2*>(&pk.x));
        float2 f23 = __half22float2(*reinterpret_cast<__half2*>(&pk.y));
        acc.x = fmaf(wgt, f01.x, acc.x);
        acc.y = fmaf(wgt, f01.y, acc.y);
        acc.z = fmaf(wgt, f23.x, acc.z);
        acc.w = fmaf(wgt, f23.y, acc.w);
    }

    float inv = (e1 > e0) ? (1.f / ssum) : 0.f;
    float4 o = make_float4(acc.x * inv, acc.y * inv, acc.z * inv, acc.w * inv);

    if (hres) {
        float4 r = __ldg(&reinterpret_cast<const float4*>(hres)[n * 32 + lane]);
        o.x += r.x; o.y += r.y; o.z += r.z; o.w += r.w;
    }
    if (do_act) {  // ELU(alpha=1)
        o.x = (o.x > 0.f) ? o.x : expm1f(o.x);
        o.y = (o.y > 0.f) ? o.y : expm1f(o.y);
        o.z = (o.z > 0.f) ? o.z : expm1f(o.z);
        o.w = (o.w > 0.f) ? o.w : expm1f(o.w);
    }

    if (do_mean) {
        o.x += __shfl_xor_sync(0xffffffffu, o.x, 8);
        o.y += __shfl_xor_sync(0xffffffffu, o.y, 8);
        o.z += __shfl_xor_sync(0xffffffffu, o.z, 8);
        o.w += __shfl_xor_sync(0xffffffffu, o.w, 8);
        o.x += __shfl_xor_sync(0xffffffffu, o.x, 16);
        o.y += __shfl_xor_sync(0xffffffffu, o.y, 16);
        o.z += __shfl_xor_sync(0xffffffffu, o.z, 16);
        o.w += __shfl_xor_sync(0xffffffffu, o.w, 16);
        if (lane < 8) {
            reinterpret_cast<float4*>(out)[n * 8 + lane] =
                make_float4(o.x * 0.25f, o.y * 0.25f, o.z * 0.25f, o.w * 0.25f);
        }
    } else {
        reinterpret_cast<float4*>(out)[n * 32 + lane] = o;
    }
}

// ---------------- launcher --------------------------------------------------
extern "C" void kernel_launch(void* const* d_in, const int* in_sizes, int n_in,
                              void* d_out, int out_size)
{
    const float* x   = (const float*)d_in[0];
    const int*   src = (const int*)d_in[1];
    const int*   dst = (const int*)d_in[2];
    const float* W0  = (const float*)d_in[3];
    const float* al0 = (const float*)d_in[4];
    const float* ar0 = (const float*)d_in[5];
    const float* W1  = (const float*)d_in[6];
    const float* al1 = (const float*)d_in[7];
    const float* ar1 = (const float*)d_in[8];
    const float* W2  = (const float*)d_in[9];
    const float* al2 = (const float*)d_in[10];
    const float* ar2 = (const float*)d_in[11];
    float* out = (float*)d_out;

    float *h1 = nullptr, *h2 = nullptr;
    cudaGetSymbolAddress((void**)&h1, g_h1);
    cudaGetSymbolAddress((void**)&h2, g_h2);

    const int gemm_grid = (NN + RPB - 1) / RPB;   // 782
    const int agg_grid  = (NN * 32) / 256;        // 6250 (exact)

    rowptr_kernel<<<(NN + 1 + 255) / 256, 256>>>(dst);

    // layer 0: no residual, ELU
    gemm_attn_kernel<<<gemm_grid, 256>>>(x, W0, al0, ar0);
    gat_agg_kernel<<<agg_grid, 256>>>(src, nullptr, h1, /*act=*/1, /*mean=*/0);

    // layer 1: residual (input h1), ELU
    gemm_attn_kernel<<<gemm_grid, 256>>>(h1, W1, al1, ar1);
    gat_agg_kernel<<<agg_grid, 256>>>(src, h1, h2, /*act=*/1, /*mean=*/0);

    // layer 2: residual (input h2), no act, mean over heads -> [N, 32]
    gemm_attn_kernel<<<gemm_grid, 256>>>(h2, W2, al2, ar2);
    gat_agg_kernel<<<agg_grid, 256>>>(src, h2, out, /*act=*/0, /*mean=*/1);
}